// round 16
// baseline (speedup 1.0000x reference)
#include <cuda_runtime.h>
#include <cuda_fp16.h>

// Problem constants
#define BATCH 32
#define IMG_H 480
#define IMG_W 640
#define OUT_H 470
#define OUT_W 630
#define WS    11

// Tiling: 32 wide x 120 tall (4 row-bands cover 480 exactly)
#define TILE_W 32
#define TILE_H 120
#define IN_W   (TILE_W + WS - 1)   // 42
#define IN_W_PAD 44                // multiple of 4 for vector loads
#define IN_H   (TILE_H + WS - 1)   // 130
#define MID_W  TILE_W              // 32

#define GX 20   // ceil(630/32)
#define GY 4    // 4 * 120 = 480 rows
#define NBLOCKS (GX * GY * BATCH)  // 2560
#define NTHREADS 640

#define H2W 8                                  // stage-2 strip width
#define N_STRIPS2 (IN_H * (TILE_W / H2W))      // 520 strips, single pass
#define H3 6                                   // stage-3 strip height
#define N_STRIPS3 ((TILE_H / H3) * TILE_W)     // 640 strips == NTHREADS exactly

// Normalized 1D Gaussian, sigma=1.5, ws=11 (symmetric)
static __device__ __forceinline__ float gw(int t) {
    constexpr float w[11] = {
        0.00102839f, 0.00759866f, 0.03600077f, 0.10936124f, 0.21300553f,
        0.26601172f,
        0.21300553f, 0.10936124f, 0.03600077f, 0.00759866f, 0.00102839f
    };
    return w[t];
}

static __device__ __forceinline__ unsigned h2u(__half2 h) { return *(unsigned*)&h; }
static __device__ __forceinline__ __half2  u2h(unsigned u) { return *(__half2*)&u; }

__device__ float        g_partials[NBLOCKS];
__device__ unsigned int g_count = 0;

__global__ __launch_bounds__(NTHREADS, 2)
void ssim_tile_kernel(const float* __restrict__ img1,
                      const float* __restrict__ img2,
                      float* __restrict__ out)
{
    extern __shared__ float smem[];
    // s_sd: packed half2(s,d) per pixel. 4B/px.
    unsigned* s_sd  = (unsigned*)smem;                    // IN_H * IN_W_PAD
    uint2*    s_mid = (uint2*)(s_sd + IN_H * IN_W_PAD);   // IN_H*MID_W: (h2(Ms,Md), h2(Es,Ed))

    __shared__ float    s_red[NTHREADS / 32];
    __shared__ unsigned s_flag;

    const int tid = threadIdx.x;
    const int bz  = blockIdx.z;
    const int r0  = blockIdx.y * TILE_H;
    const int c0  = blockIdx.x * TILE_W;

    const float* im1 = img1 + (size_t)bz * IMG_H * IMG_W;
    const float* im2 = img2 + (size_t)bz * IMG_H * IMG_W;

    // ---- Stage 1: load tile (with halo), store packed half2(s, d) ----
    if (c0 + IN_W_PAD <= IMG_W) {
        // quad path: full-width rows (c0 mult of 32, IMG_W mult of 4 -> 16B aligned);
        // bottom-band blocks get per-row guard, OOB rows -> 0
        const int NQ = IN_W_PAD / 4;   // 11 quads per row
        for (int i = tid; i < IN_H * NQ; i += NTHREADS) {
            int r = i / NQ;
            int q = i - r * NQ;
            int gr = r0 + r;
            float4 a = make_float4(0.f, 0.f, 0.f, 0.f);
            float4 b = a;
            if (gr < IMG_H) {
                a = ((const float4*)(im1 + (size_t)gr * IMG_W + c0))[q];
                b = ((const float4*)(im2 + (size_t)gr * IMG_W + c0))[q];
            }
            uint4 packed;
            packed.x = h2u(__floats2half2_rn(a.x + b.x, a.x - b.x));
            packed.y = h2u(__floats2half2_rn(a.y + b.y, a.y - b.y));
            packed.z = h2u(__floats2half2_rn(a.z + b.z, a.z - b.z));
            packed.w = h2u(__floats2half2_rn(a.w + b.w, a.w - b.w));
            ((uint4*)(s_sd + r * IN_W_PAD))[q] = packed;   // STS.128
        }
    } else {
        // right-edge blocks (bx = GX-1): scalar guarded path
        for (int i = tid; i < IN_H * IN_W_PAD; i += NTHREADS) {
            int r = i / IN_W_PAD;
            int c = i - r * IN_W_PAD;
            int gr = r0 + r;
            int gc = c0 + c;
            float v1 = 0.f, v2 = 0.f;
            if (gr < IMG_H && gc < IMG_W) {
                int idx = gr * IMG_W + gc;
                v1 = im1[idx];
                v2 = im2[idx];
            }
            s_sd[r * IN_W_PAD + c] = h2u(__floats2half2_rn(v1 + v2, v1 - v2));
        }
    }
    __syncthreads();

    // ---- Stage 2: horizontal conv in half2 (HFMA2), 8-wide strips, ONE pass ----
    // 520 strips (130 rows x 4 octets); 5 x LDS.128 per strip.
    if (tid < N_STRIPS2) {
        __half2 wh[WS];
        #pragma unroll
        for (int t = 0; t < WS; t++)
            wh[t] = __floats2half2_rn(gw(t), gw(t));

        int row = tid >> 2;           // tid / 4
        int cq  = (tid & 3) << 3;     // (tid % 4) * 8

        // 20 packed (s,d) half2; taps use first 18
        const uint4* p4 = (const uint4*)(s_sd + row * IN_W_PAD + cq);
        unsigned pv[20];
        #pragma unroll
        for (int i = 0; i < 5; i++) {
            uint4 u = p4[i];
            pv[4*i+0] = u.x; pv[4*i+1] = u.y; pv[4*i+2] = u.z; pv[4*i+3] = u.w;
        }

        __half2 aM[H2W], aE[H2W];
        #pragma unroll
        for (int o = 0; o < H2W; o++) {
            aM[o] = __floats2half2_rn(0.f, 0.f);
            aE[o] = __floats2half2_rn(0.f, 0.f);
        }

        #pragma unroll
        for (int k = 0; k < WS + H2W - 1; k++) {   // 18 taps serve 8 outputs
            __half2 pk  = u2h(pv[k]);        // (s, d)
            __half2 psq = __hmul2(pk, pk);   // (s^2, d^2)
            #pragma unroll
            for (int o = 0; o < H2W; o++) {
                int t = k - o;
                if (t >= 0 && t < WS) {      // compile-time resolved
                    aM[o] = __hfma2(wh[t], pk,  aM[o]);
                    aE[o] = __hfma2(wh[t], psq, aE[o]);
                }
            }
        }
        // accumulators are already the mid format: 4 x STS.128, no cvt
        uint4* m4 = (uint4*)(s_mid + row * MID_W + cq);
        #pragma unroll
        for (int o = 0; o < 4; o++)
            m4[o] = make_uint4(h2u(aM[2*o]), h2u(aE[2*o]),
                               h2u(aM[2*o+1]), h2u(aE[2*o+1]));
    }
    __syncthreads();

    // ---- Stage 3: vertical conv in half2 (HFMA2) + fp32 SSIM epilogue ----
    // 640 strips == 640 threads; 16 taps serve 6 outputs; batched preloads.
    const float C1 = 1.0f;   // (0.01*100)^2
    const float C2 = 9.0f;   // (0.03*100)^2
    float lsum = 0.f;

    {
        int c  = tid & (TILE_W - 1);
        int rq = (tid >> 5) * H3;

        __half2 wh[WS];
        #pragma unroll
        for (int t = 0; t < WS; t++)
            wh[t] = __floats2half2_rn(gw(t), gw(t));

        __half2 accM[H3], accE[H3];
        #pragma unroll
        for (int o = 0; o < H3; o++) {
            accM[o] = __floats2half2_rn(0.f, 0.f);
            accE[o] = __floats2half2_rn(0.f, 0.f);
        }

        // two batches of 8 back-to-back LDS.64: MLP hides latency
        #pragma unroll
        for (int half = 0; half < 2; half++) {
            uint2 buf[8];
            #pragma unroll
            for (int j = 0; j < 8; j++)
                buf[j] = s_mid[(rq + half * 8 + j) * MID_W + c];
            #pragma unroll
            for (int j = 0; j < 8; j++) {
                int k = half * 8 + j;
                __half2 vm = u2h(buf[j].x);
                __half2 ve = u2h(buf[j].y);
                #pragma unroll
                for (int o = 0; o < H3; o++) {
                    int t = k - o;
                    if (t >= 0 && t < WS) {
                        accM[o] = __hfma2(wh[t], vm, accM[o]);
                        accE[o] = __hfma2(wh[t], ve, accE[o]);
                    }
                }
            }
        }

        int gc = c0 + c;
        if (gc < OUT_W) {
            #pragma unroll
            for (int o = 0; o < H3; o++) {
                int gr = r0 + rq + o;
                if (gr < OUT_H) {
                    float2 M = __half22float2(accM[o]);
                    float2 E = __half22float2(accE[o]);
                    float ms = M.x, md = M.y;
                    float ms2 = ms * ms;
                    float md2 = md * md;
                    float Ps = E.x - ms2;     // s1+s2+2*s12
                    float Qd = E.y - md2;     // s1+s2-2*s12
                    float v1 = 0.5f * (Ps - Qd) + C2;            // 2*s12 + C2
                    float v2 = 0.5f * (Ps + Qd) + C2;            // s1+s2 + C2
                    float num = (0.5f * (ms2 - md2) + C1) * v1;  // (2*mu12+C1)*v1
                    float den = (0.5f * (ms2 + md2) + C1) * v2;  // (mu1^2+mu2^2+C1)*v2
                    lsum += __fdividef(num, den);
                }
            }
        }
    }

    // ---- Stage 4: block partial + fused last-block finalize ----
    #pragma unroll
    for (int off = 16; off > 0; off >>= 1)
        lsum += __shfl_down_sync(0xffffffffu, lsum, off);

    int warp = tid >> 5;
    int lane = tid & 31;
    if (lane == 0) s_red[warp] = lsum;
    __syncthreads();
    if (tid == 0) {
        float t = 0.f;
        #pragma unroll
        for (int i = 0; i < NTHREADS / 32; i++) t += s_red[i];
        int bidx = (blockIdx.z * GY + blockIdx.y) * GX + blockIdx.x;
        g_partials[bidx] = t;
        __threadfence();
        unsigned v = atomicAdd(&g_count, 1u);
        s_flag = (v == (unsigned)(NBLOCKS - 1));
    }
    __syncthreads();

    if (s_flag) {
        // deterministic: fixed summation order independent of which block runs this
        float acc = 0.f;
        for (int i = tid; i < NBLOCKS; i += NTHREADS)
            acc += __ldcg(&g_partials[i]);
        #pragma unroll
        for (int off = 16; off > 0; off >>= 1)
            acc += __shfl_down_sync(0xffffffffu, acc, off);
        if (lane == 0) s_red[warp] = acc;
        __syncthreads();
        if (tid == 0) {
            float tt = 0.f;
            #pragma unroll
            for (int i = 0; i < NTHREADS / 32; i++) tt += s_red[i];
            float mean = tt * (1.0f / ((float)BATCH * OUT_H * OUT_W));
            out[0] = (1.0f - mean) * 0.5f;
            g_count = 0;   // reset for next graph replay
        }
    }
}

extern "C" void kernel_launch(void* const* d_in, const int* in_sizes, int n_in,
                              void* d_out, int out_size)
{
    const float* img1 = (const float*)d_in[0];
    const float* img2 = (const float*)d_in[1];
    float* out = (float*)d_out;

    size_t smem_bytes = (size_t)(IN_H * IN_W_PAD) * sizeof(unsigned)
                      + (size_t)(IN_H * MID_W) * sizeof(uint2);
    cudaFuncSetAttribute(ssim_tile_kernel,
                         cudaFuncAttributeMaxDynamicSharedMemorySize,
                         (int)smem_bytes);

    dim3 grid(GX, GY, BATCH);
    ssim_tile_kernel<<<grid, NTHREADS, smem_bytes>>>(img1, img2, out);
}

// round 17
// speedup vs baseline: 1.2007x; 1.2007x over previous
#include <cuda_runtime.h>
#include <cuda_fp16.h>

// Problem constants
#define BATCH 32
#define IMG_H 480
#define IMG_W 640
#define OUT_H 470
#define OUT_W 630
#define WS    11

// Tiling: 32 wide x 120 tall (4 row-bands cover 480 exactly)
#define TILE_W 32
#define TILE_H 120
#define IN_W   (TILE_W + WS - 1)   // 42
#define IN_W_PAD 44                // multiple of 4 for vector loads
#define IN_H   (TILE_H + WS - 1)   // 130
#define MID_W  TILE_W              // 32

#define GX 20   // ceil(630/32)
#define GY 4    // 4 * 120 = 480 rows
#define NBLOCKS (GX * GY * BATCH)  // 2560
#define NTHREADS 640

#define H3 6                                 // stage-3 strip height
#define N_STRIPS3 ((TILE_H / H3) * TILE_W)   // 640 strips == NTHREADS exactly

// Normalized 1D Gaussian, sigma=1.5, ws=11 (symmetric)
static __device__ __forceinline__ float gw(int t) {
    constexpr float w[11] = {
        0.00102839f, 0.00759866f, 0.03600077f, 0.10936124f, 0.21300553f,
        0.26601172f,
        0.21300553f, 0.10936124f, 0.03600077f, 0.00759866f, 0.00102839f
    };
    return w[t];
}

static __device__ __forceinline__ unsigned h2u(__half2 h) { return *(unsigned*)&h; }
static __device__ __forceinline__ __half2  u2h(unsigned u) { return *(__half2*)&u; }

__device__ float        g_partials[NBLOCKS];
__device__ unsigned int g_count = 0;

__global__ __launch_bounds__(NTHREADS, 3)
void ssim_tile_kernel(const float* __restrict__ img1,
                      const float* __restrict__ img2,
                      float* __restrict__ out)
{
    extern __shared__ float smem[];
    // s_sd: packed half2(s,d) per pixel. 4B/px.
    unsigned* s_sd  = (unsigned*)smem;                    // IN_H * IN_W_PAD
    uint2*    s_mid = (uint2*)(s_sd + IN_H * IN_W_PAD);   // IN_H*MID_W: (h2(Ms,Md), h2(Es,Ed))

    __shared__ float    s_red[NTHREADS / 32];
    __shared__ unsigned s_flag;

    const int tid = threadIdx.x;
    const int bz  = blockIdx.z;
    const int r0  = blockIdx.y * TILE_H;
    const int c0  = blockIdx.x * TILE_W;

    const float* im1 = img1 + (size_t)bz * IMG_H * IMG_W;
    const float* im2 = img2 + (size_t)bz * IMG_H * IMG_W;

    // ---- Stage 1: load tile (with halo), store packed half2(s, d) ----
    if (c0 + IN_W_PAD <= IMG_W) {
        // quad path: full-width rows (c0 mult of 32, IMG_W mult of 4 -> 16B aligned);
        // bottom-band blocks get per-row guard, OOB rows -> 0
        const int NQ = IN_W_PAD / 4;   // 11 quads per row
        for (int i = tid; i < IN_H * NQ; i += NTHREADS) {
            int r = i / NQ;
            int q = i - r * NQ;
            int gr = r0 + r;
            float4 a = make_float4(0.f, 0.f, 0.f, 0.f);
            float4 b = a;
            if (gr < IMG_H) {
                a = ((const float4*)(im1 + (size_t)gr * IMG_W + c0))[q];
                b = ((const float4*)(im2 + (size_t)gr * IMG_W + c0))[q];
            }
            uint4 packed;
            packed.x = h2u(__floats2half2_rn(a.x + b.x, a.x - b.x));
            packed.y = h2u(__floats2half2_rn(a.y + b.y, a.y - b.y));
            packed.z = h2u(__floats2half2_rn(a.z + b.z, a.z - b.z));
            packed.w = h2u(__floats2half2_rn(a.w + b.w, a.w - b.w));
            ((uint4*)(s_sd + r * IN_W_PAD))[q] = packed;   // STS.128
        }
    } else {
        // right-edge blocks (bx = GX-1): scalar guarded path
        for (int i = tid; i < IN_H * IN_W_PAD; i += NTHREADS) {
            int r = i / IN_W_PAD;
            int c = i - r * IN_W_PAD;
            int gr = r0 + r;
            int gc = c0 + c;
            float v1 = 0.f, v2 = 0.f;
            if (gr < IMG_H && gc < IMG_W) {
                int idx = gr * IMG_W + gc;
                v1 = im1[idx];
                v2 = im2[idx];
            }
            s_sd[r * IN_W_PAD + c] = h2u(__floats2half2_rn(v1 + v2, v1 - v2));
        }
    }
    __syncthreads();

    // ---- Stage 2: horizontal conv in half2 (HFMA2), 4-wide strips ----
    // 1040 strips (130 rows x 8 quads); 4 x LDS.128 per strip (lane-distinct 16B).
    {
        __half2 wh[WS];
        #pragma unroll
        for (int t = 0; t < WS; t++)
            wh[t] = __floats2half2_rn(gw(t), gw(t));

        for (int st = tid; st < IN_H * (TILE_W / 4); st += NTHREADS) {
            int row = st >> 3;            // st / 8
            int cq  = (st & 7) << 2;      // (st % 8) * 4

            // 16 packed (s,d) half2; taps use first 14
            const uint4* p4 = (const uint4*)(s_sd + row * IN_W_PAD + cq);
            unsigned pv[16];
            #pragma unroll
            for (int i = 0; i < 4; i++) {
                uint4 u = p4[i];
                pv[4*i+0] = u.x; pv[4*i+1] = u.y; pv[4*i+2] = u.z; pv[4*i+3] = u.w;
            }

            __half2 aM[4], aE[4];
            #pragma unroll
            for (int o = 0; o < 4; o++) {
                aM[o] = __floats2half2_rn(0.f, 0.f);
                aE[o] = __floats2half2_rn(0.f, 0.f);
            }

            #pragma unroll
            for (int k = 0; k < WS + 3; k++) {   // 14 taps serve 4 outputs
                __half2 pk  = u2h(pv[k]);        // (s, d)
                __half2 psq = __hmul2(pk, pk);   // (s^2, d^2)
                #pragma unroll
                for (int o = 0; o < 4; o++) {
                    int t = k - o;
                    if (t >= 0 && t < WS) {      // compile-time resolved
                        aM[o] = __hfma2(wh[t], pk,  aM[o]);
                        aE[o] = __hfma2(wh[t], psq, aE[o]);
                    }
                }
            }
            // accumulators are already the mid format: 2 x STS.128, no cvt
            uint4* m4 = (uint4*)(s_mid + row * MID_W + cq);
            m4[0] = make_uint4(h2u(aM[0]), h2u(aE[0]), h2u(aM[1]), h2u(aE[1]));
            m4[1] = make_uint4(h2u(aM[2]), h2u(aE[2]), h2u(aM[3]), h2u(aE[3]));
        }
    }
    __syncthreads();

    // ---- Stage 3: vertical conv in half2 (HFMA2) + fp32 SSIM epilogue ----
    // 640 strips == 640 threads; 16 taps serve 6 outputs; 1 LDS.64 per tap.
    const float C1 = 1.0f;   // (0.01*100)^2
    const float C2 = 9.0f;   // (0.03*100)^2
    float lsum = 0.f;

    {
        int c  = tid & (TILE_W - 1);
        int rq = (tid >> 5) * H3;

        __half2 wh[WS];
        #pragma unroll
        for (int t = 0; t < WS; t++)
            wh[t] = __floats2half2_rn(gw(t), gw(t));

        __half2 accM[H3], accE[H3];
        #pragma unroll
        for (int o = 0; o < H3; o++) {
            accM[o] = __floats2half2_rn(0.f, 0.f);
            accE[o] = __floats2half2_rn(0.f, 0.f);
        }

        #pragma unroll
        for (int k = 0; k < WS + H3 - 1; k++) {   // 16 taps
            uint2 u = s_mid[(rq + k) * MID_W + c];   // LDS.64, conflict-free
            __half2 vm = u2h(u.x);
            __half2 ve = u2h(u.y);
            #pragma unroll
            for (int o = 0; o < H3; o++) {
                int t = k - o;
                if (t >= 0 && t < WS) {
                    accM[o] = __hfma2(wh[t], vm, accM[o]);
                    accE[o] = __hfma2(wh[t], ve, accE[o]);
                }
            }
        }

        int gc = c0 + c;
        if (gc < OUT_W) {
            #pragma unroll
            for (int o = 0; o < H3; o++) {
                int gr = r0 + rq + o;
                if (gr < OUT_H) {
                    float2 M = __half22float2(accM[o]);
                    float2 E = __half22float2(accE[o]);
                    float ms = M.x, md = M.y;
                    float ms2 = ms * ms;
                    float md2 = md * md;
                    float Ps = E.x - ms2;     // s1+s2+2*s12
                    float Qd = E.y - md2;     // s1+s2-2*s12
                    float v1 = 0.5f * (Ps - Qd) + C2;            // 2*s12 + C2
                    float v2 = 0.5f * (Ps + Qd) + C2;            // s1+s2 + C2
                    float num = (0.5f * (ms2 - md2) + C1) * v1;  // (2*mu12+C1)*v1
                    float den = (0.5f * (ms2 + md2) + C1) * v2;  // (mu1^2+mu2^2+C1)*v2
                    lsum += __fdividef(num, den);
                }
            }
        }
    }

    // ---- Stage 4: block partial + fused last-block finalize ----
    #pragma unroll
    for (int off = 16; off > 0; off >>= 1)
        lsum += __shfl_down_sync(0xffffffffu, lsum, off);

    int warp = tid >> 5;
    int lane = tid & 31;
    if (lane == 0) s_red[warp] = lsum;
    __syncthreads();
    if (tid == 0) {
        float t = 0.f;
        #pragma unroll
        for (int i = 0; i < NTHREADS / 32; i++) t += s_red[i];
        int bidx = (blockIdx.z * GY + blockIdx.y) * GX + blockIdx.x;
        g_partials[bidx] = t;
        __threadfence();
        unsigned v = atomicAdd(&g_count, 1u);
        s_flag = (v == (unsigned)(NBLOCKS - 1));
    }
    __syncthreads();

    if (s_flag) {
        // deterministic: fixed summation order independent of which block runs this
        float acc = 0.f;
        for (int i = tid; i < NBLOCKS; i += NTHREADS)
            acc += __ldcg(&g_partials[i]);
        #pragma unroll
        for (int off = 16; off > 0; off >>= 1)
            acc += __shfl_down_sync(0xffffffffu, acc, off);
        if (lane == 0) s_red[warp] = acc;
        __syncthreads();
        if (tid == 0) {
            float tt = 0.f;
            #pragma unroll
            for (int i = 0; i < NTHREADS / 32; i++) tt += s_red[i];
            float mean = tt * (1.0f / ((float)BATCH * OUT_H * OUT_W));
            out[0] = (1.0f - mean) * 0.5f;
            g_count = 0;   // reset for next graph replay
        }
    }
}

extern "C" void kernel_launch(void* const* d_in, const int* in_sizes, int n_in,
                              void* d_out, int out_size)
{
    const float* img1 = (const float*)d_in[0];
    const float* img2 = (const float*)d_in[1];
    float* out = (float*)d_out;

    size_t smem_bytes = (size_t)(IN_H * IN_W_PAD) * sizeof(unsigned)
                      + (size_t)(IN_H * MID_W) * sizeof(uint2);
    cudaFuncSetAttribute(ssim_tile_kernel,
                         cudaFuncAttributeMaxDynamicSharedMemorySize,
                         (int)smem_bytes);

    dim3 grid(GX, GY, BATCH);
    ssim_tile_kernel<<<grid, NTHREADS, smem_bytes>>>(img1, img2, out);
}